// round 1
// baseline (speedup 1.0000x reference)
#include <cuda_runtime.h>
#include <cuda_fp16.h>
#include <cstdint>
#include <cstddef>

#define BATCH 4096
#define NN    36
#define CX    64
#define CH    128
#define CC    192
#define KC    768
#define ROWS  (BATCH*NN)   // 147456
#define OUT1  256
#define OUT2  128

// ---------------- scratch (static device globals; no allocation) -------------
static __device__ __half g_GX[(size_t)BATCH*NN*256];   // [b][n][ord*64+cx]
static __device__ __half g_GH[(size_t)BATCH*NN*512];   // [b][n][ord*128+ch]
static __device__ __half g_D [(size_t)BATCH*NN*512];   // [b][n][ord*128+o] (ord0 = r*h)
static __device__ float  g_U [(size_t)BATCH*CH*NN];    // u gate, [b][o][n]
static __device__ __half g_Wfu[OUT1*KC];               // reordered f|u weights
static __device__ __half g_Wc2[OUT2*KC];               // reordered c weights
static __device__ float  g_Mp[3*NN*NN];                // M, M^2, M^3 ; M[n][w]=adj[w][n]

// ---------------- K0: adjacency powers --------------------------------------
__global__ void k_adjpow(const float* __restrict__ adj) {
    __shared__ float M[NN*NN], M2[NN*NN];
    int t = threadIdx.x;
    for (int i = t; i < NN*NN; i += blockDim.x) {
        int n = i / NN, w = i % NN;
        float v = adj[w*NN + n];          // M = adj^T
        M[i] = v; g_Mp[i] = v;
    }
    __syncthreads();
    for (int i = t; i < NN*NN; i += blockDim.x) {
        int n = i / NN, w = i % NN; float s = 0.f;
        #pragma unroll
        for (int m = 0; m < NN; m++) s = fmaf(M[n*NN+m], M[m*NN+w], s);
        M2[i] = s; g_Mp[NN*NN + i] = s;
    }
    __syncthreads();
    for (int i = t; i < NN*NN; i += blockDim.x) {
        int n = i / NN, w = i % NN; float s = 0.f;
        #pragma unroll
        for (int m = 0; m < NN; m++) s = fmaf(M2[n*NN+m], M[m*NN+w], s);
        g_Mp[2*NN*NN + i] = s;
    }
}

// ---------------- KW: reorder+convert weights to fp16 ------------------------
// new kc layout: [0,256) = ord*64+cx  (x part),  [256,768) = ord*128+ch (h part)
__global__ void k_wprep(const float* __restrict__ Wf, const float* __restrict__ Wu,
                        const float* __restrict__ Wc) {
    int idx = blockIdx.x * blockDim.x + threadIdx.x;
    const int total1 = OUT1 * KC;                  // 196608
    if (idx < total1) {
        int j = idx / KC, kc = idx % KC;
        int src;
        if (kc < 256) { int ord = kc >> 6, cx = kc & 63; src = ord*CC + cx; }
        else { int tt = kc - 256; int ord = tt >> 7, ch = tt & 127; src = ord*CC + CX + ch; }
        float v = (j < 128) ? Wf[j*KC + src] : Wu[(j-128)*KC + src];
        g_Wfu[idx] = __float2half(v);
    } else {
        int idx2 = idx - total1;
        if (idx2 < OUT2 * KC) {
            int j = idx2 / KC, kc = idx2 % KC;
            int src;
            if (kc < 256) { int ord = kc >> 6, cx = kc & 63; src = ord*CC + cx; }
            else { int tt = kc - 256; int ord = tt >> 7, ch = tt & 127; src = ord*CC + CX + ch; }
            g_Wc2[idx2] = __float2half(Wc[j*KC + src]);
        }
    }
}

// ---------------- K1: diffusion of x and h -----------------------------------
// one CTA per batch, 192 threads = one channel each; z row cached in registers
__global__ void k_diff1(const float* __restrict__ x, const float* __restrict__ h) {
    __shared__ float Mp[3*NN*NN];
    const int b = blockIdx.x, t = threadIdx.x;
    for (int i = t; i < 3*NN*NN; i += 192) Mp[i] = g_Mp[i];
    __syncthreads();

    const bool isx = (t < CX);
    const int c = isx ? t : (t - CX);
    const float* src = isx ? (x + ((size_t)b*CX + c)*NN)
                           : (h + ((size_t)b*CH + c)*NN);
    float z[NN];
    #pragma unroll
    for (int n = 0; n < NN; n++) z[n] = src[n];

    __half* out = isx ? (g_GX + (size_t)b*NN*256) : (g_GH + (size_t)b*NN*512);
    const int stride = isx ? 256 : 512;
    const int cs     = isx ? 64  : 128;

    #pragma unroll
    for (int w = 0; w < NN; w++) out[w*stride + c] = __float2half(z[w]);   // order 0
    for (int ord = 1; ord < 4; ord++) {
        const float* Mo = &Mp[(ord-1)*NN*NN];
        for (int w = 0; w < NN; w++) {
            float s = 0.f;
            #pragma unroll
            for (int n = 0; n < NN; n++) s = fmaf(z[n], Mo[n*NN + w], s);
            out[w*stride + ord*cs + c] = __float2half(s);
        }
    }
}

// ---------------- K3: diffusion of r*h (order-0 already in g_D) --------------
__global__ void k_diff2() {
    __shared__ float Mp[3*NN*NN];
    const int b = blockIdx.x, t = threadIdx.x;   // t = channel o, 128 threads
    for (int i = t; i < 3*NN*NN; i += 128) Mp[i] = g_Mp[i];
    __syncthreads();

    __half* base = g_D + (size_t)b*NN*512;
    float z[NN];
    #pragma unroll
    for (int n = 0; n < NN; n++) z[n] = __half2float(base[n*512 + t]);

    for (int ord = 1; ord < 4; ord++) {
        const float* Mo = &Mp[(ord-1)*NN*NN];
        for (int w = 0; w < NN; w++) {
            float s = 0.f;
            #pragma unroll
            for (int n = 0; n < NN; n++) s = fmaf(z[n], Mo[n*NN + w], s);
            base[w*512 + ord*128 + t] = __float2half(s);
        }
    }
}

// ---------------- K2/K4: fp16 MMA GEMM + fused epilogues ---------------------
// out[j, r] = sum_kc W[j][kc] * G[r][kc], r=(b,n); K=768 split 256(GX)+512(GH/D)
// CTA tile 128(M=j) x 128(N=r), 8 warps (4 M x 2 N), warp tile 32x64, KT=32.
__global__ __launch_bounds__(256) void k_gemm(
    const float* __restrict__ hin,
    const float* __restrict__ bfp, const float* __restrict__ bup,
    const float* __restrict__ bcp, float* __restrict__ outp, const int epi)
{
    __shared__ __align__(16) __half sA[2][128][40];   // [m][k], pad 8 halves
    __shared__ __align__(16) __half sB[2][128][40];   // [n][k]

    const int tid  = threadIdx.x;
    const int warp = tid >> 5, lane = tid & 31;
    const int g = lane >> 2, t4 = lane & 3;
    const int warpM = (warp & 3) * 32;
    const int warpN = (warp >> 2) * 64;
    const int j0 = blockIdx.x * 128;
    const int r0 = blockIdx.y * 128;

    const __half* __restrict__ Ap = (epi == 1) ? g_Wfu : g_Wc2;
    const __half* __restrict__ BH = (epi == 1) ? g_GH  : g_D;

    float acc[2][8][4];
    #pragma unroll
    for (int mi = 0; mi < 2; mi++)
        #pragma unroll
        for (int ni = 0; ni < 8; ni++)
            #pragma unroll
            for (int q = 0; q < 4; q++) acc[mi][ni][q] = 0.f;

    uint4 aR[2], bR[2];
    auto gload = [&](int it) {
        const int kc0 = it * 32;
        const __half* Bp; int bs, col;
        if (kc0 < 256) { Bp = g_GX; bs = 256; col = kc0; }
        else           { Bp = BH;   bs = 512; col = kc0 - 256; }
        #pragma unroll
        for (int q = 0; q < 2; q++) {
            int u = tid*2 + q; int row = u >> 2; int seg = u & 3;
            aR[q] = *(const uint4*)(Ap + (size_t)(j0 + row)*KC + kc0 + seg*8);
            bR[q] = *(const uint4*)(Bp + (size_t)(r0 + row)*bs + col  + seg*8);
        }
    };
    auto sstore = [&](int buf) {
        #pragma unroll
        for (int q = 0; q < 2; q++) {
            int u = tid*2 + q; int row = u >> 2; int seg = u & 3;
            *(uint4*)&sA[buf][row][seg*8] = aR[q];
            *(uint4*)&sB[buf][row][seg*8] = bR[q];
        }
    };

    gload(0); sstore(0); __syncthreads();

    for (int it = 0; it < 24; it++) {
        const int buf = it & 1;
        if (it < 23) gload(it + 1);
        #pragma unroll
        for (int kk = 0; kk < 32; kk += 16) {
            uint32_t af[2][4];
            #pragma unroll
            for (int mi = 0; mi < 2; mi++) {
                int r = warpM + mi*16 + g;
                af[mi][0] = *(const uint32_t*)&sA[buf][r    ][kk + 2*t4];
                af[mi][1] = *(const uint32_t*)&sA[buf][r + 8][kk + 2*t4];
                af[mi][2] = *(const uint32_t*)&sA[buf][r    ][kk + 2*t4 + 8];
                af[mi][3] = *(const uint32_t*)&sA[buf][r + 8][kk + 2*t4 + 8];
            }
            uint32_t bf2[8][2];
            #pragma unroll
            for (int ni = 0; ni < 8; ni++) {
                int cn = warpN + ni*8 + g;
                bf2[ni][0] = *(const uint32_t*)&sB[buf][cn][kk + 2*t4];
                bf2[ni][1] = *(const uint32_t*)&sB[buf][cn][kk + 2*t4 + 8];
            }
            #pragma unroll
            for (int mi = 0; mi < 2; mi++)
                #pragma unroll
                for (int ni = 0; ni < 8; ni++)
                    asm volatile(
                        "mma.sync.aligned.m16n8k16.row.col.f32.f16.f16.f32 "
                        "{%0,%1,%2,%3}, {%4,%5,%6,%7}, {%8,%9}, {%0,%1,%2,%3};\n"
                        : "+f"(acc[mi][ni][0]), "+f"(acc[mi][ni][1]),
                          "+f"(acc[mi][ni][2]), "+f"(acc[mi][ni][3])
                        : "r"(af[mi][0]), "r"(af[mi][1]),
                          "r"(af[mi][2]), "r"(af[mi][3]),
                          "r"(bf2[ni][0]), "r"(bf2[ni][1]));
        }
        if (it < 23) sstore(buf ^ 1);
        __syncthreads();
    }

    // ---------------- epilogue ----------------
    #pragma unroll
    for (int mi = 0; mi < 2; mi++) {
        #pragma unroll
        for (int ni = 0; ni < 8; ni++) {
            const int rr = r0 + warpN + ni*8 + 2*t4;   // even -> (rr, rr+1) same batch
            const int bb = rr / NN;
            const int n  = rr - bb * NN;
            #pragma unroll
            for (int hf = 0; hf < 2; hf++) {
                const int j = j0 + warpM + mi*16 + g + hf*8;
                float v0 = acc[mi][ni][hf*2 + 0];
                float v1 = acc[mi][ni][hf*2 + 1];
                if (epi == 1) {
                    const float bias = (j < 128) ? bfp[j] : bup[j - 128];
                    v0 = 1.f / (1.f + __expf(-(v0 + bias)));
                    v1 = 1.f / (1.f + __expf(-(v1 + bias)));
                    if (j < 128) {        // r gate -> r*h into D order 0
                        const float2 hh = *(const float2*)&hin[((size_t)bb*CH + j)*NN + n];
                        g_D[((size_t)bb*NN + n    )*512 + j] = __float2half(v0 * hh.x);
                        g_D[((size_t)bb*NN + n + 1)*512 + j] = __float2half(v1 * hh.y);
                    } else {              // u gate
                        float2 uv; uv.x = v0; uv.y = v1;
                        *(float2*)&g_U[((size_t)bb*CH + (j-128))*NN + n] = uv;
                    }
                } else {
                    const float cb = bcp[j];
                    const float c0 = tanhf(v0 + cb);
                    const float c1 = tanhf(v1 + cb);
                    const size_t off = ((size_t)bb*CH + j)*NN + n;
                    const float2 uu = *(const float2*)&g_U[off];
                    const float2 hh = *(const float2*)&hin[off];
                    float2 oo;
                    oo.x = uu.x*hh.x + (1.f - uu.x)*c0;
                    oo.y = uu.y*hh.y + (1.f - uu.y)*c1;
                    *(float2*)&outp[off] = oo;
                }
            }
        }
    }
}

// ---------------- launcher ----------------------------------------------------
extern "C" void kernel_launch(void* const* d_in, const int* in_sizes, int n_in,
                              void* d_out, int out_size) {
    (void)in_sizes; (void)n_in; (void)out_size;
    const float* x   = (const float*)d_in[0];
    const float* h   = (const float*)d_in[1];
    const float* adj = (const float*)d_in[2];
    const float* Wf  = (const float*)d_in[3];
    const float* bf  = (const float*)d_in[4];
    const float* Wu  = (const float*)d_in[5];
    const float* bu  = (const float*)d_in[6];
    const float* Wc  = (const float*)d_in[7];
    const float* bc  = (const float*)d_in[8];
    float* out = (float*)d_out;

    k_adjpow<<<1, 256>>>(adj);
    k_wprep<<<1152, 256>>>(Wf, Wu, Wc);
    k_diff1<<<BATCH, 192>>>(x, h);
    k_gemm<<<dim3(2, ROWS/128), 256>>>(h, bf, bu, bc, out, 1);
    k_diff2<<<BATCH, 128>>>();
    k_gemm<<<dim3(1, ROWS/128), 256>>>(h, bf, bu, bc, out, 2);
}

// round 4
// speedup vs baseline: 1.2901x; 1.2901x over previous
#include <cuda_runtime.h>
#include <cuda_fp16.h>
#include <cstdint>
#include <cstddef>

#define BATCH 4096
#define NN    36
#define CX    64
#define CH    128
#define CC    192
#define KC    768
#define ROWS  (BATCH*NN)   // 147456
#define OUT1  256
#define OUT2  128

// ---------------- scratch (static device globals; no allocation) -------------
static __device__ __align__(128) __half g_GX[(size_t)BATCH*NN*256];   // [b][n][ord*64+cx]
static __device__ __align__(128) __half g_GH[(size_t)BATCH*NN*512];   // [b][n][ord*128+ch]
static __device__ __align__(128) __half g_D [(size_t)BATCH*NN*512];   // [b][n][ord*128+o] (ord0 = r*h)
static __device__ __align__(128) float  g_U [(size_t)BATCH*CH*NN];    // u gate, [b][o][n]
static __device__ __align__(128) __half g_Wfu[OUT1*KC];               // reordered f|u weights
static __device__ __align__(128) __half g_Wc2[OUT2*KC];               // reordered c weights
static __device__ __align__(128) float  g_Mp[3*NN*NN];                // M, M^2, M^3 ; M[n][w]=adj[w][n]

// ---------------- K0: adjacency powers --------------------------------------
__global__ void k_adjpow(const float* __restrict__ adj) {
    __shared__ float M[NN*NN], M2[NN*NN];
    int t = threadIdx.x;
    for (int i = t; i < NN*NN; i += blockDim.x) {
        int n = i / NN, w = i % NN;
        float v = adj[w*NN + n];          // M = adj^T
        M[i] = v; g_Mp[i] = v;
    }
    __syncthreads();
    for (int i = t; i < NN*NN; i += blockDim.x) {
        int n = i / NN, w = i % NN; float s = 0.f;
        #pragma unroll
        for (int m = 0; m < NN; m++) s = fmaf(M[n*NN+m], M[m*NN+w], s);
        M2[i] = s; g_Mp[NN*NN + i] = s;
    }
    __syncthreads();
    for (int i = t; i < NN*NN; i += blockDim.x) {
        int n = i / NN, w = i % NN; float s = 0.f;
        #pragma unroll
        for (int m = 0; m < NN; m++) s = fmaf(M2[n*NN+m], M[m*NN+w], s);
        g_Mp[2*NN*NN + i] = s;
    }
}

// ---------------- KW: reorder+convert weights to fp16 ------------------------
// new kc layout: [0,256) = ord*64+cx  (x part),  [256,768) = ord*128+ch (h part)
__global__ void k_wprep(const float* __restrict__ Wf, const float* __restrict__ Wu,
                        const float* __restrict__ Wc) {
    int idx = blockIdx.x * blockDim.x + threadIdx.x;
    const int total1 = OUT1 * KC;                  // 196608
    if (idx < total1) {
        int j = idx / KC, kc = idx % KC;
        int src;
        if (kc < 256) { int ord = kc >> 6, cx = kc & 63; src = ord*CC + cx; }
        else { int tt = kc - 256; int ord = tt >> 7, ch = tt & 127; src = ord*CC + CX + ch; }
        float v = (j < 128) ? Wf[j*KC + src] : Wu[(j-128)*KC + src];
        g_Wfu[idx] = __float2half(v);
    } else {
        int idx2 = idx - total1;
        if (idx2 < OUT2 * KC) {
            int j = idx2 / KC, kc = idx2 % KC;
            int src;
            if (kc < 256) { int ord = kc >> 6, cx = kc & 63; src = ord*CC + cx; }
            else { int tt = kc - 256; int ord = tt >> 7, ch = tt & 127; src = ord*CC + CX + ch; }
            g_Wc2[idx2] = __float2half(Wc[j*KC + src]);
        }
    }
}

// ============ f32x2 helpers ==================================================
__device__ __forceinline__ unsigned long long pack_dup_f32(float v) {
    unsigned long long r; unsigned int b = __float_as_uint(v);
    asm("mov.b64 %0, {%1, %1};" : "=l"(r) : "r"(b));
    return r;
}
__device__ __forceinline__ void fma_f32x2(unsigned long long& acc,
                                          unsigned long long a, unsigned long long b) {
    asm("fma.rn.f32x2 %0, %1, %2, %0;" : "+l"(acc) : "l"(a), "l"(b));
}
__device__ __forceinline__ void unpack_f32x2(unsigned long long v, float& lo, float& hi) {
    unsigned int l, h;
    asm("mov.b64 {%0, %1}, %2;" : "=r"(l), "=r"(h) : "l"(v));
    lo = __uint_as_float(l); hi = __uint_as_float(h);
}

// ---------------- K1: diffusion of x and h -----------------------------------
// one CTA per batch, 192 threads = one channel each; coalesced staged loads,
// f32x2 packed FMA over w-pairs, M pairs via LDS.64.
__global__ __launch_bounds__(192) void k_diff1(const float* __restrict__ x,
                                               const float* __restrict__ h) {
    __shared__ float Mp[3*NN*NN];      // 15552 B
    __shared__ float sZ[192*37];       // 28416 B, stride 37 (conflict-free reads)
    const int b = blockIdx.x, t = threadIdx.x;
    for (int i = t; i < 3*NN*NN; i += 192) Mp[i] = g_Mp[i];

    // coalesced staging (36 = 9 float4 per channel row; no row crossing)
    const float4* x4 = (const float4*)(x + (size_t)b*CX*NN);
    for (int i = t; i < (CX*NN)/4; i += 192) {          // 576
        float4 v = x4[i];
        int c = i / 9, n0 = (i % 9) * 4;
        float* d = &sZ[c*37 + n0];
        d[0] = v.x; d[1] = v.y; d[2] = v.z; d[3] = v.w;
    }
    const float4* h4 = (const float4*)(h + (size_t)b*CH*NN);
    for (int i = t; i < (CH*NN)/4; i += 192) {          // 1152
        float4 v = h4[i];
        int c = 64 + i / 9, n0 = (i % 9) * 4;
        float* d = &sZ[c*37 + n0];
        d[0] = v.x; d[1] = v.y; d[2] = v.z; d[3] = v.w;
    }
    __syncthreads();

    float z[NN];
    #pragma unroll
    for (int n = 0; n < NN; n++) z[n] = sZ[t*37 + n];

    const bool isx = (t < CX);
    const int c = isx ? t : (t - CX);
    __half* out = isx ? (g_GX + (size_t)b*NN*256) : (g_GH + (size_t)b*NN*512);
    const int stride = isx ? 256 : 512;
    const int cs     = isx ? 64  : 128;

    #pragma unroll
    for (int w = 0; w < NN; w++) out[w*stride + c] = __float2half(z[w]);   // order 0

    #pragma unroll
    for (int ord = 1; ord < 4; ord++) {
        const float* Mo = &Mp[(ord-1)*NN*NN];
        unsigned long long acc[18];
        #pragma unroll
        for (int wp = 0; wp < 18; wp++) acc[wp] = 0ULL;
        #pragma unroll
        for (int n = 0; n < NN; n++) {
            unsigned long long zz = pack_dup_f32(z[n]);
            #pragma unroll
            for (int wp = 0; wp < 18; wp++) {
                unsigned long long mm = *(const unsigned long long*)&Mo[n*NN + 2*wp];
                fma_f32x2(acc[wp], zz, mm);
            }
        }
        #pragma unroll
        for (int wp = 0; wp < 18; wp++) {
            float lo, hi; unpack_f32x2(acc[wp], lo, hi);
            out[(2*wp  )*stride + ord*cs + c] = __float2half(lo);
            out[(2*wp+1)*stride + ord*cs + c] = __float2half(hi);
        }
    }
}

// ---------------- K3: diffusion of r*h (order-0 already in g_D) --------------
__global__ __launch_bounds__(128) void k_diff2() {
    __shared__ float Mp[3*NN*NN];
    const int b = blockIdx.x, t = threadIdx.x;   // t = channel o, 128 threads
    for (int i = t; i < 3*NN*NN; i += 128) Mp[i] = g_Mp[i];
    __syncthreads();

    __half* base = g_D + (size_t)b*NN*512;
    float z[NN];
    #pragma unroll
    for (int n = 0; n < NN; n++) z[n] = __half2float(base[n*512 + t]);

    #pragma unroll
    for (int ord = 1; ord < 4; ord++) {
        const float* Mo = &Mp[(ord-1)*NN*NN];
        unsigned long long acc[18];
        #pragma unroll
        for (int wp = 0; wp < 18; wp++) acc[wp] = 0ULL;
        #pragma unroll
        for (int n = 0; n < NN; n++) {
            unsigned long long zz = pack_dup_f32(z[n]);
            #pragma unroll
            for (int wp = 0; wp < 18; wp++) {
                unsigned long long mm = *(const unsigned long long*)&Mo[n*NN + 2*wp];
                fma_f32x2(acc[wp], zz, mm);
            }
        }
        #pragma unroll
        for (int wp = 0; wp < 18; wp++) {
            float lo, hi; unpack_f32x2(acc[wp], lo, hi);
            base[(2*wp  )*512 + ord*128 + t] = __float2half(lo);
            base[(2*wp+1)*512 + ord*128 + t] = __float2half(hi);
        }
    }
}

// ---------------- K2/K4: fp16 MMA GEMM (cp.async + ldmatrix) -----------------
// out[j, r] = sum_kc W[j][kc] * G[r][kc], r=(b,n); K=768 split 256(GX)+512(GH/D)
// CTA tile 128(M=j) x 128(N=r), 8 warps (4M x 2N), warp tile 32x64.
// K-step 16, 3-stage cp.async pipeline, ldmatrix.x4 fragments.
#define KT   16
#define PADH 24     // 48B rows: 16B-aligned + conflict-free ldmatrix
#define NSTG 3

__global__ __launch_bounds__(256, 2) void k_gemm(
    const float* __restrict__ hin,
    const float* __restrict__ bfp, const float* __restrict__ bup,
    const float* __restrict__ bcp, float* __restrict__ outp, const int epi)
{
    __shared__ __align__(16) __half sA[NSTG][128][PADH];   // 18432 B
    __shared__ __align__(16) __half sB[NSTG][128][PADH];   // 18432 B

    const int tid  = threadIdx.x;
    const int warp = tid >> 5, lane = tid & 31;
    const int g = lane >> 2, t4 = lane & 3;
    const int warpM = (warp & 3) * 32;
    const int warpN = (warp >> 2) * 64;
    const int j0 = blockIdx.x * 128;
    const int r0 = blockIdx.y * 128;

    const __half* __restrict__ Ap = (epi == 1) ? g_Wfu : g_Wc2;
    const __half* __restrict__ BH = (epi == 1) ? g_GH  : g_D;

    // cp.async: per thread one 16B chunk per array per stage
    const int crow = tid >> 1;              // 0..127
    const int cseg = (tid & 1) * 8;         // half offset within row
    const uint32_t sAb = (uint32_t)__cvta_generic_to_shared(&sA[0][0][0]);
    const uint32_t sBb = (uint32_t)__cvta_generic_to_shared(&sB[0][0][0]);
    const uint32_t stB = 128 * PADH * 2;    // stage stride bytes
    const uint32_t cOff = (uint32_t)(crow * PADH + cseg) * 2;

    // ldmatrix lane->row/col mapping
    const int lm = lane >> 3, lr = lane & 7;
    const int aRowB = warpM + ((lm & 1) ? 8 : 0) + lr;  const int aCol = (lm >= 2) ? 8 : 0;
    const int bRowB = warpN + ((lm >= 2) ? 8 : 0) + lr; const int bCol = (lm & 1) ? 8 : 0;

    float acc[2][8][4];
    #pragma unroll
    for (int mi = 0; mi < 2; mi++)
        #pragma unroll
        for (int ni = 0; ni < 8; ni++)
            #pragma unroll
            for (int q = 0; q < 4; q++) acc[mi][ni][q] = 0.f;

    auto issue = [&](int it) {
        const int kc0 = it * KT;
        const int st  = it % NSTG;
        const __half* Bp; int bs, col;
        if (kc0 < 256) { Bp = g_GX; bs = 256; col = kc0; }
        else           { Bp = BH;   bs = 512; col = kc0 - 256; }
        const uint32_t da = sAb + st * stB + cOff;
        const uint32_t db = sBb + st * stB + cOff;
        const __half* ga = Ap + (size_t)(j0 + crow) * KC + kc0 + cseg;
        const __half* gb = Bp + (size_t)(r0 + crow) * bs + col + cseg;
        asm volatile("cp.async.cg.shared.global [%0], [%1], 16;\n" :: "r"(da), "l"(ga));
        asm volatile("cp.async.cg.shared.global [%0], [%1], 16;\n" :: "r"(db), "l"(gb));
        asm volatile("cp.async.commit_group;\n");
    };

    issue(0); issue(1); issue(2);

    for (int it = 0; it < KC/KT; it++) {
        asm volatile("cp.async.wait_group 2;\n");
        __syncthreads();
        const int st = it % NSTG;
        const uint32_t aBase = sAb + st * stB;
        const uint32_t bBase = sBb + st * stB;

        uint32_t af[2][4];
        #pragma unroll
        for (int mi = 0; mi < 2; mi++) {
            uint32_t addr = aBase + (uint32_t)((aRowB + mi*16) * PADH + aCol) * 2;
            asm volatile("ldmatrix.sync.aligned.m8n8.x4.shared.b16 {%0,%1,%2,%3}, [%4];\n"
                : "=r"(af[mi][0]), "=r"(af[mi][1]), "=r"(af[mi][2]), "=r"(af[mi][3])
                : "r"(addr));
        }
        uint32_t bf[8][2];
        #pragma unroll
        for (int p = 0; p < 4; p++) {
            uint32_t addr = bBase + (uint32_t)((bRowB + p*16) * PADH + bCol) * 2;
            uint32_t q0, q1, q2, q3;
            asm volatile("ldmatrix.sync.aligned.m8n8.x4.shared.b16 {%0,%1,%2,%3}, [%4];\n"
                : "=r"(q0), "=r"(q1), "=r"(q2), "=r"(q3) : "r"(addr));
            bf[2*p  ][0] = q0; bf[2*p  ][1] = q1;
            bf[2*p+1][0] = q2; bf[2*p+1][1] = q3;
        }
        #pragma unroll
        for (int mi = 0; mi < 2; mi++)
            #pragma unroll
            for (int ni = 0; ni < 8; ni++)
                asm volatile(
                    "mma.sync.aligned.m16n8k16.row.col.f32.f16.f16.f32 "
                    "{%0,%1,%2,%3}, {%4,%5,%6,%7}, {%8,%9}, {%0,%1,%2,%3};\n"
                    : "+f"(acc[mi][ni][0]), "+f"(acc[mi][ni][1]),
                      "+f"(acc[mi][ni][2]), "+f"(acc[mi][ni][3])
                    : "r"(af[mi][0]), "r"(af[mi][1]),
                      "r"(af[mi][2]), "r"(af[mi][3]),
                      "r"(bf[ni][0]), "r"(bf[ni][1]));
        __syncthreads();
        if (it + NSTG < KC/KT) issue(it + NSTG);
    }

    // ---------------- epilogue ----------------
    #pragma unroll
    for (int mi = 0; mi < 2; mi++) {
        #pragma unroll
        for (int ni = 0; ni < 8; ni++) {
            const int rr = r0 + warpN + ni*8 + 2*t4;   // even -> (rr, rr+1) same batch
            const int bb = rr / NN;
            const int n  = rr - bb * NN;
            #pragma unroll
            for (int hf = 0; hf < 2; hf++) {
                const int j = j0 + warpM + mi*16 + g + hf*8;
                float v0 = acc[mi][ni][hf*2 + 0];
                float v1 = acc[mi][ni][hf*2 + 1];
                if (epi == 1) {
                    const float bias = (j < 128) ? bfp[j] : bup[j - 128];
                    v0 = 1.f / (1.f + __expf(-(v0 + bias)));
                    v1 = 1.f / (1.f + __expf(-(v1 + bias)));
                    if (j < 128) {        // r gate -> r*h into D order 0
                        const float2 hh = *(const float2*)&hin[((size_t)bb*CH + j)*NN + n];
                        g_D[((size_t)bb*NN + n    )*512 + j] = __float2half(v0 * hh.x);
                        g_D[((size_t)bb*NN + n + 1)*512 + j] = __float2half(v1 * hh.y);
                    } else {              // u gate
                        float2 uv; uv.x = v0; uv.y = v1;
                        *(float2*)&g_U[((size_t)bb*CH + (j-128))*NN + n] = uv;
                    }
                } else {
                    const float cb = bcp[j];
                    const float c0 = tanhf(v0 + cb);
                    const float c1 = tanhf(v1 + cb);
                    const size_t off = ((size_t)bb*CH + j)*NN + n;
                    const float2 uu = *(const float2*)&g_U[off];
                    const float2 hh = *(const float2*)&hin[off];
                    float2 oo;
                    oo.x = uu.x*hh.x + (1.f - uu.x)*c0;
                    oo.y = uu.y*hh.y + (1.f - uu.y)*c1;
                    *(float2*)&outp[off] = oo;
                }
            }
        }
    }
}

// ---------------- launcher ----------------------------------------------------
extern "C" void kernel_launch(void* const* d_in, const int* in_sizes, int n_in,
                              void* d_out, int out_size) {
    (void)in_sizes; (void)n_in; (void)out_size;
    const float* x   = (const float*)d_in[0];
    const float* h   = (const float*)d_in[1];
    const float* adj = (const float*)d_in[2];
    const float* Wf  = (const float*)d_in[3];
    const float* bf  = (const float*)d_in[4];
    const float* Wu  = (const float*)d_in[5];
    const float* bu  = (const float*)d_in[6];
    const float* Wc  = (const float*)d_in[7];
    const float* bc  = (const float*)d_in[8];
    float* out = (float*)d_out;

    k_adjpow<<<1, 256>>>(adj);
    k_wprep<<<1152, 256>>>(Wf, Wu, Wc);
    k_diff1<<<BATCH, 192>>>(x, h);
    k_gemm<<<dim3(2, ROWS/128), 256>>>(h, bf, bu, bc, out, 1);
    k_diff2<<<BATCH, 128>>>();
    k_gemm<<<dim3(1, ROWS/128), 256>>>(h, bf, bu, bc, out, 2);
}